// round 13
// baseline (speedup 1.0000x reference)
#include <cuda_runtime.h>
#include <math.h>

// Problem dims (fixed by reference setup_inputs)
#define BB 2048
#define KK 8
#define OO 256
#define II 512
#define TINY 1e-10f

// Scratch (no allocations allowed)
__device__ int d_kstar[BB];
__device__ int d_order[BB];

// ---------------- prep: select + hist + scan + scatter, ONE block ----------------
__global__ void k_prep(const float* __restrict__ mixw,
                       const float* __restrict__ u) {
    __shared__ int hist[KK];
    __shared__ int soff[KK];
    __shared__ float w[KK];
    const int t = threadIdx.x;
    if (t < KK) { hist[t] = 0; w[t] = mixw[t]; }
    __syncthreads();

    int kst[2];
#pragma unroll
    for (int r = 0; r < 2; r++) {
        const int b = t + r * 1024;
        float4 u0 = reinterpret_cast<const float4*>(u + b * KK)[0];
        float4 u1 = reinterpret_cast<const float4*>(u + b * KK)[1];
        float uu[KK] = {u0.x, u0.y, u0.z, u0.w, u1.x, u1.y, u1.z, u1.w};
        float best = -1e30f;
        int bi = 0;
#pragma unroll
        for (int k = 0; k < KK; k++) {
            float g = -logf(-logf(uu[k] + TINY) + TINY);
            float sc = w[k] + g;           // TAU = 1
            if (sc > best) { best = sc; bi = k; }
        }
        kst[r] = bi;
        d_kstar[b] = bi;
        atomicAdd(&hist[bi], 1);
    }
    __syncthreads();
    if (t == 0) {
        int acc = 0;
#pragma unroll
        for (int k = 0; k < KK; k++) { soff[k] = acc; acc += hist[k]; }
    }
    __syncthreads();
#pragma unroll
    for (int r = 0; r < 2; r++) {
        int pos = atomicAdd(&soff[kst[r]], 1);
        d_order[pos] = t + r * 1024;
    }
}

// ---------------- cp.async helpers ----------------
__device__ __forceinline__ void cp16(void* smem_dst, const void* gsrc) {
    unsigned s = (unsigned)__cvta_generic_to_shared(smem_dst);
    asm volatile("cp.async.cg.shared.global [%0], [%1], 16;" :: "r"(s), "l"(gsrc));
}
#define CP_COMMIT() asm volatile("cp.async.commit_group;" ::: "memory")
#define CP_WAIT(n)  asm volatile("cp.async.wait_group %0;" :: "n"(n) : "memory")

// ---------------- main kernel: PERSISTENT, cross-tile pipeline ----------------
// 256 blocks. Block bid owns fixed o-tile ox = bid&31 (warp w -> o = ox*8+w)
// and 16 b-tiles: by(i) = (bid>>5) + i*8, i = 0..15  (covers all 128 by's,
// perfectly balanced). One continuous pipeline of G = 256 iterations:
//   - eps: warp-local slices, 3 smem slots, lookahead 2, flows across tile
//     boundaries with NO drain (prologue/drain paid once per block, not 16x).
//   - X: double-buffered 32KB tiles, prefetched 2 iterations before use
//     (merged into the group whose wait lands exactly at the tile's j==0).
//   - one __syncthreads per tile (16 iters): publishes the new X buffer and
//     bounds warp skew to <1 tile so buffer reuse is WAR-safe. cp.async
//     groups stay in flight across it.
//   - bs/ks via per-warp __ldg of tiny L1-hot d_order/d_kstar: no smem, no
//     extra barriers.
// Fixed ox => mean/exp(log_sigma) reloads only on true k-changes over the
// whole block lifetime (~10 instead of ~16).

#define TB 16
#define SLOTS 3
#define NT 16
#define GRIDN 256

__global__ __launch_bounds__(256, 2)
void k_main(const float* __restrict__ X,
            const float* __restrict__ mean,
            const float* __restrict__ log_sigma,
            const float* __restrict__ eps,
            float* __restrict__ out) {
    __shared__ float Xs[2][TB][II];              // 64 KB (double buffer)
    __shared__ float es[SLOTS][8 * II];          // 48 KB

    const int tid  = threadIdx.x;
    const int warp = tid >> 5;
    const int lane = tid & 31;
    const int ox   = blockIdx.x & 31;
    const int grp  = blockIdx.x >> 5;            // 0..7
    const int o    = ox * 8 + warp;

    auto j0_of = [&](int i) { return (grp + i * 8) * TB; };

    // warp-local: stage eps row (b(g), o, :) into es[g%SLOTS][warp*II]
    auto issue_eps = [&](int g) {
        const int i = g >> 4, j = g & 15;
        const int b = __ldg(&d_order[j0_of(i) + j]);
        const float* base = eps + ((size_t)b * OO + o) * II;
        float* dst = &es[g % SLOTS][warp * II];
#pragma unroll
        for (int c = 0; c < 4; c++) {
            int f = c * 32 + lane;               // matches read pattern
            cp16(dst + f * 4, base + f * 4);
        }
    };

    // block-wide: stage tile i's X (16 rows) into Xs[i&1]
    auto issue_X = [&](int i) {
#pragma unroll
        for (int r = 0; r < 8; r++) {
            int v = tid + r * 256;               // 0..2047 float4s
            int row = v >> 7;                    // /128
            int i4  = v & 127;
            int b = __ldg(&d_order[j0_of(i) + row]);
            cp16(&Xs[i & 1][row][i4 * 4], X + (size_t)b * II + i4 * 4);
        }
    };

    // prologue: group0 = X(tile0) + eps(g=0); group1 = eps(g=1)
    issue_X(0); issue_eps(0); CP_COMMIT();
    issue_eps(1);             CP_COMMIT();

    int curk = -1;
    float4 m[4], s[4];

    const int G = NT * TB;                       // 256
#pragma unroll 1
    for (int g = 0; g < G; g++) {
        const int i = g >> 4, j = g & 15;

        CP_WAIT(1);              // this thread's group g complete
        if (j == 0)
            __syncthreads();     // tile boundary: publish Xs[i&1], bound skew

        // issue group g+2 (eps for g+2; plus next tile's X when it aligns)
        if (g + 2 < G) {
            if (((g + 2) & 15) == 0)
                issue_X((g + 2) >> 4);           // into Xs[((g+2)>>4)&1]
            issue_eps(g + 2);
        }
        CP_COMMIT();             // uniform accounting (empty at the tail)

        const int b = __ldg(&d_order[j0_of(i) + j]);
        const int k = __ldg(&d_kstar[b]);
        if (k != curk) {         // uniform per warp; rare (fixed ox + sort)
            curk = k;
            const float4* mp = reinterpret_cast<const float4*>(
                mean + ((size_t)(k * OO + o)) * II);
            const float4* lp = reinterpret_cast<const float4*>(
                log_sigma + ((size_t)(k * OO + o)) * II);
#pragma unroll
            for (int c = 0; c < 4; c++) {
                int idx = c * 32 + lane;
                m[c] = mp[idx];
                float4 l = lp[idx];
                s[c] = make_float4(expf(l.x), expf(l.y), expf(l.z), expf(l.w));
            }
        }

        const float4* ep = reinterpret_cast<const float4*>(&es[g % SLOTS][warp * II]);
        const float4* xp = reinterpret_cast<const float4*>(&Xs[i & 1][j][0]);

        float a0 = 0.f, a1 = 0.f, a2 = 0.f, a3 = 0.f;
        {
            float4 e = ep[0 * 32 + lane];
            float4 x = xp[0 * 32 + lane];
            a0 = fmaf(x.x, fmaf(s[0].x, e.x, m[0].x), a0);
            a0 = fmaf(x.y, fmaf(s[0].y, e.y, m[0].y), a0);
            a0 = fmaf(x.z, fmaf(s[0].z, e.z, m[0].z), a0);
            a0 = fmaf(x.w, fmaf(s[0].w, e.w, m[0].w), a0);
        }
        {
            float4 e = ep[1 * 32 + lane];
            float4 x = xp[1 * 32 + lane];
            a1 = fmaf(x.x, fmaf(s[1].x, e.x, m[1].x), a1);
            a1 = fmaf(x.y, fmaf(s[1].y, e.y, m[1].y), a1);
            a1 = fmaf(x.z, fmaf(s[1].z, e.z, m[1].z), a1);
            a1 = fmaf(x.w, fmaf(s[1].w, e.w, m[1].w), a1);
        }
        {
            float4 e = ep[2 * 32 + lane];
            float4 x = xp[2 * 32 + lane];
            a2 = fmaf(x.x, fmaf(s[2].x, e.x, m[2].x), a2);
            a2 = fmaf(x.y, fmaf(s[2].y, e.y, m[2].y), a2);
            a2 = fmaf(x.z, fmaf(s[2].z, e.z, m[2].z), a2);
            a2 = fmaf(x.w, fmaf(s[2].w, e.w, m[2].w), a2);
        }
        {
            float4 e = ep[3 * 32 + lane];
            float4 x = xp[3 * 32 + lane];
            a3 = fmaf(x.x, fmaf(s[3].x, e.x, m[3].x), a3);
            a3 = fmaf(x.y, fmaf(s[3].y, e.y, m[3].y), a3);
            a3 = fmaf(x.z, fmaf(s[3].z, e.z, m[3].z), a3);
            a3 = fmaf(x.w, fmaf(s[3].w, e.w, m[3].w), a3);
        }
        float acc = (a0 + a1) + (a2 + a3);

#pragma unroll
        for (int off = 16; off > 0; off >>= 1)
            acc += __shfl_xor_sync(0xFFFFFFFFu, acc, off);
        if (lane == 0)
            out[(size_t)b * OO + o] = acc;
    }
}

// ---------------- launch ----------------

extern "C" void kernel_launch(void* const* d_in, const int* in_sizes, int n_in,
                              void* d_out, int out_size) {
    (void)in_sizes; (void)n_in; (void)out_size;
    const float* X    = (const float*)d_in[0];
    const float* mixw = (const float*)d_in[1];
    const float* mean = (const float*)d_in[2];
    const float* lsig = (const float*)d_in[3];
    const float* u    = (const float*)d_in[4];
    const float* eps  = (const float*)d_in[5];
    float* out = (float*)d_out;

    k_prep<<<1, 1024>>>(mixw, u);
    k_main<<<GRIDN, 256>>>(X, mean, lsig, eps, out);
}

// round 15
// speedup vs baseline: 1.1624x; 1.1624x over previous
#include <cuda_runtime.h>
#include <math.h>

// Problem dims (fixed by reference setup_inputs)
#define BB 2048
#define KK 8
#define OO 256
#define II 512
#define TINY 1e-10f

// Scratch (no allocations allowed)
__device__ int d_kstar[BB];
__device__ int d_order[BB];

// ---------------- prep: select + hist + scan + scatter, ONE block ----------------
// Fast path: mix_weights is uniform, and g(u) = -log(-log(u+eps)+eps) is
// strictly monotone in u, so argmax_k(w_k + g_k) == argmax_k u_k. No MUFU.
// Runtime-checks uniformity; logf fallback otherwise.
__global__ void k_prep(const float* __restrict__ mixw,
                       const float* __restrict__ u) {
    __shared__ int hist[KK];
    __shared__ int soff[KK];
    __shared__ float w[KK];
    const int t = threadIdx.x;
    if (t < KK) { hist[t] = 0; w[t] = mixw[t]; }
    __syncthreads();

    bool uni = true;
#pragma unroll
    for (int k = 1; k < KK; k++) uni &= (w[k] == w[0]);

    int kst[2];
#pragma unroll
    for (int r = 0; r < 2; r++) {
        const int b = t + r * 1024;
        float4 u0 = reinterpret_cast<const float4*>(u + b * KK)[0];
        float4 u1 = reinterpret_cast<const float4*>(u + b * KK)[1];
        float uu[KK] = {u0.x, u0.y, u0.z, u0.w, u1.x, u1.y, u1.z, u1.w};
        float best = -1e30f;
        int bi = 0;
        if (uni) {
#pragma unroll
            for (int k = 0; k < KK; k++)
                if (uu[k] > best) { best = uu[k]; bi = k; }
        } else {
#pragma unroll
            for (int k = 0; k < KK; k++) {
                float g = -logf(-logf(uu[k] + TINY) + TINY);
                float sc = w[k] + g;       // TAU = 1
                if (sc > best) { best = sc; bi = k; }
            }
        }
        kst[r] = bi;
        d_kstar[b] = bi;
        atomicAdd(&hist[bi], 1);
    }
    __syncthreads();
    if (t == 0) {
        int acc = 0;
#pragma unroll
        for (int k = 0; k < KK; k++) { soff[k] = acc; acc += hist[k]; }
    }
    __syncthreads();
#pragma unroll
    for (int r = 0; r < 2; r++) {
        int pos = atomicAdd(&soff[kst[r]], 1);
        d_order[pos] = t + r * 1024;
    }
}

// ---------------- cp.async helpers ----------------
__device__ __forceinline__ void cp16(void* smem_dst, const void* gsrc) {
    unsigned s = (unsigned)__cvta_generic_to_shared(smem_dst);
    asm volatile("cp.async.cg.shared.global [%0], [%1], 16;" :: "r"(s), "l"(gsrc));
}
#define CP_COMMIT() asm volatile("cp.async.commit_group;" ::: "memory")
#define CP_WAIT(n)  asm volatile("cp.async.wait_group %0;" :: "n"(n) : "memory")

// ---------------- main kernel (R9 shape, occupancy 3) ----------------
// grid: (OO/8, BB/TB) = (32, 256) = 8192 blocks. 8 warps/block, warp w owns
// o = bx*8 + w. WARP-LOCAL eps pipeline: warp w stages only its own 2KB row
// slice into es[slot][w*II], lane l copying exactly the float4s c*32+l it
// later reads -> zero steady-state barriers (per-thread cp.async.wait_group
// is the only ordering). TB=8 + 3 slots shrinks smem to 64KB/block so THREE
// blocks fit per SM (24 warps, vs 16 in R9): more independent warps cover
// the latency of each warp's k-reload/shuffle serial tail, and per-SM
// in-flight cp.async bytes rise 64KB -> 96KB.

#define TB 8
#define SLOTS 3

__global__ __launch_bounds__(256, 3)
void k_main(const float* __restrict__ X,
            const float* __restrict__ mean,
            const float* __restrict__ log_sigma,
            const float* __restrict__ eps,
            float* __restrict__ out) {
    __shared__ float Xs[TB][II];                 // 16 KB
    __shared__ float es[SLOTS][8 * II];          // 48 KB
    __shared__ int bs[TB];
    __shared__ int ks[TB];

    const int tid  = threadIdx.x;
    const int warp = tid >> 5;
    const int lane = tid & 31;
    const int o    = blockIdx.x * 8 + warp;
    const int j0   = blockIdx.y * TB;

    if (tid < TB) {
        int b = d_order[j0 + tid];
        bs[tid] = b;
        ks[tid] = d_kstar[b];
    }
    __syncthreads();            // bs/ks visible before any issue

    // warp-local: stage eps row (bs[j], o, :) into es[j%SLOTS][warp*II]
    auto issue_eps = [&](int j) {
        const float* base = eps + ((size_t)bs[j] * OO + o) * II;
        float* dst = &es[j % SLOTS][warp * II];
#pragma unroll
        for (int c = 0; c < 4; c++) {
            int f = c * 32 + lane;              // matches read pattern exactly
            cp16(dst + f * 4, base + f * 4);
        }
    };

    // prologue: group0 = X tile + eps(0); group1 = eps(1)
    {
#pragma unroll
        for (int r = 0; r < 4; r++) {
            int v = tid + r * 256;              // 0..1023 float4s
            int row = v >> 7;
            int i4  = v & 127;
            cp16(&Xs[row][i4 * 4], X + (size_t)bs[row] * II + i4 * 4);
        }
        issue_eps(0);
        CP_COMMIT();
        issue_eps(1);
        CP_COMMIT();
    }

    int curk = -1;
    float4 m[4], s[4];

#pragma unroll 1
    for (int j = 0; j < TB; j++) {
        CP_WAIT(1);             // per-thread: group j complete (j=0: + X tile)
        if (j == 0)
            __syncthreads();    // publish X to all warps (one-time)

        // issue batch j+2 into slot (j+2)%3 = (j-1)%3 (consumed at j-1;
        // same-thread same-address ordering makes the WAR safe)
        if (j + 2 < TB)
            issue_eps(j + 2);
        CP_COMMIT();            // uniform one-commit-per-iter accounting

        const int k = ks[j];
        if (k != curk) {        // uniform across warp; rare after sort
            curk = k;
            const float4* mp = reinterpret_cast<const float4*>(
                mean + ((size_t)(k * OO + o)) * II);
            const float4* lp = reinterpret_cast<const float4*>(
                log_sigma + ((size_t)(k * OO + o)) * II);
#pragma unroll
            for (int c = 0; c < 4; c++) {
                int idx = c * 32 + lane;
                m[c] = mp[idx];
                float4 l = lp[idx];
                s[c] = make_float4(expf(l.x), expf(l.y), expf(l.z), expf(l.w));
            }
        }

        const float4* ep = reinterpret_cast<const float4*>(&es[j % SLOTS][warp * II]);
        const float4* xp = reinterpret_cast<const float4*>(&Xs[j][0]);

        float a0 = 0.f, a1 = 0.f, a2 = 0.f, a3 = 0.f;
        {
            float4 e = ep[0 * 32 + lane];
            float4 x = xp[0 * 32 + lane];
            a0 = fmaf(x.x, fmaf(s[0].x, e.x, m[0].x), a0);
            a0 = fmaf(x.y, fmaf(s[0].y, e.y, m[0].y), a0);
            a0 = fmaf(x.z, fmaf(s[0].z, e.z, m[0].z), a0);
            a0 = fmaf(x.w, fmaf(s[0].w, e.w, m[0].w), a0);
        }
        {
            float4 e = ep[1 * 32 + lane];
            float4 x = xp[1 * 32 + lane];
            a1 = fmaf(x.x, fmaf(s[1].x, e.x, m[1].x), a1);
            a1 = fmaf(x.y, fmaf(s[1].y, e.y, m[1].y), a1);
            a1 = fmaf(x.z, fmaf(s[1].z, e.z, m[1].z), a1);
            a1 = fmaf(x.w, fmaf(s[1].w, e.w, m[1].w), a1);
        }
        {
            float4 e = ep[2 * 32 + lane];
            float4 x = xp[2 * 32 + lane];
            a2 = fmaf(x.x, fmaf(s[2].x, e.x, m[2].x), a2);
            a2 = fmaf(x.y, fmaf(s[2].y, e.y, m[2].y), a2);
            a2 = fmaf(x.z, fmaf(s[2].z, e.z, m[2].z), a2);
            a2 = fmaf(x.w, fmaf(s[2].w, e.w, m[2].w), a2);
        }
        {
            float4 e = ep[3 * 32 + lane];
            float4 x = xp[3 * 32 + lane];
            a3 = fmaf(x.x, fmaf(s[3].x, e.x, m[3].x), a3);
            a3 = fmaf(x.y, fmaf(s[3].y, e.y, m[3].y), a3);
            a3 = fmaf(x.z, fmaf(s[3].z, e.z, m[3].z), a3);
            a3 = fmaf(x.w, fmaf(s[3].w, e.w, m[3].w), a3);
        }
        float acc = (a0 + a1) + (a2 + a3);

#pragma unroll
        for (int off = 16; off > 0; off >>= 1)
            acc += __shfl_xor_sync(0xFFFFFFFFu, acc, off);
        if (lane == 0)
            out[(size_t)bs[j] * OO + o] = acc;
    }
}

// ---------------- launch ----------------

extern "C" void kernel_launch(void* const* d_in, const int* in_sizes, int n_in,
                              void* d_out, int out_size) {
    (void)in_sizes; (void)n_in; (void)out_size;
    const float* X    = (const float*)d_in[0];
    const float* mixw = (const float*)d_in[1];
    const float* mean = (const float*)d_in[2];
    const float* lsig = (const float*)d_in[3];
    const float* u    = (const float*)d_in[4];
    const float* eps  = (const float*)d_in[5];
    float* out = (float*)d_out;

    k_prep<<<1, 1024>>>(mixw, u);

    dim3 grid(OO / 8, BB / TB);
    k_main<<<grid, 256>>>(X, mean, lsig, eps, out);
}